// round 14
// baseline (speedup 1.0000x reference)
#include <cuda_runtime.h>
#include <cuda_bf16.h>
#include <cuda_fp16.h>
#include <cstdint>
#include <math.h>

#define BB 2
#define TT 2048
#define HIDDEN 1024
#define NH 16
#define QKV_O 3072   // (16 + 2*16) * 64
#define MROWS (BB*TT) // 4096

// Scratch (allocation-free rule: __device__ globals)
__device__ float g_qkv[(size_t)MROWS * QKV_O];            // [B*T, 3072] fp32
__device__ __half g_hs_f[(size_t)MROWS * HIDDEN];
__device__ __half g_wq_h[(size_t)QKV_O * HIDDEN];
__device__ __half g_wo_h[(size_t)HIDDEN * HIDDEN];
__device__ __half g_ctx[(size_t)MROWS * HIDDEN];
// head-major fp16 attention operands: [b, h, t, d]
__device__ __half g_qf[(size_t)BB * NH * TT * 64];
__device__ __half g_kf[(size_t)BB * NH * TT * 64];
__device__ __half g_vf[(size_t)BB * NH * TT * 64];

// ===========================================================================
// Helpers
// ===========================================================================
__device__ __forceinline__ uint32_t smem_to_u32(const void* p) {
    uint32_t a;
    asm("{ .reg .u64 t; cvta.to.shared.u64 t, %1; cvt.u32.u64 %0, t; }" : "=r"(a) : "l"(p));
    return a;
}
__device__ __forceinline__ void ldsm4(unsigned* r, uint32_t addr) {
    asm volatile("ldmatrix.sync.aligned.m8n8.x4.shared.b16 {%0,%1,%2,%3}, [%4];"
                 : "=r"(r[0]), "=r"(r[1]), "=r"(r[2]), "=r"(r[3]) : "r"(addr));
}
__device__ __forceinline__ void ldsm4t(unsigned* r, uint32_t addr) {
    asm volatile("ldmatrix.sync.aligned.m8n8.x4.trans.shared.b16 {%0,%1,%2,%3}, [%4];"
                 : "=r"(r[0]), "=r"(r[1]), "=r"(r[2]), "=r"(r[3]) : "r"(addr));
}
__device__ __forceinline__ void mma_f16(float* c, const unsigned* a, unsigned b0, unsigned b1) {
    asm volatile("mma.sync.aligned.m16n8k16.row.col.f32.f16.f16.f32 "
                 "{%0,%1,%2,%3}, {%4,%5,%6,%7}, {%8,%9}, {%0,%1,%2,%3};"
                 : "+f"(c[0]), "+f"(c[1]), "+f"(c[2]), "+f"(c[3])
                 : "r"(a[0]), "r"(a[1]), "r"(a[2]), "r"(a[3]), "r"(b0), "r"(b1));
}
__device__ __forceinline__ unsigned pkH(float x, float y) {
    __half2 p(__float2half_rn(x), __float2half_rn(y));
    return *(unsigned*)&p;
}
#define CP_ASYNC16(dst, src) \
    asm volatile("cp.async.cg.shared.global [%0], [%1], 16;" :: "r"(dst), "l"(src))
#define CP_COMMIT() asm volatile("cp.async.commit_group;" ::: "memory")
#define CP_WAITG(n) asm volatile("cp.async.wait_group %0;" :: "n"(n) : "memory")

// ===========================================================================
// Converter (fp32 -> fp16)
// ===========================================================================
__global__ __launch_bounds__(256) void conv_f16(const float* __restrict__ x,
                                                __half* __restrict__ h, int n4)
{
    int i = blockIdx.x * blockDim.x + threadIdx.x;
    if (i >= n4) return;
    float4 v = ((const float4*)x)[i];
    __half2 p0 = __floats2half2_rn(v.x, v.y);
    __half2 p1 = __floats2half2_rn(v.z, v.w);
    uint2 o; o.x = *(uint32_t*)&p0; o.y = *(uint32_t*)&p1;
    ((uint2*)h)[i] = o;
}

// ===========================================================================
// Fused RoPE + layout + fp16 convert: Qf (RoPE, *0.125), Kf (RoPE), Vf
// ===========================================================================
__global__ __launch_bounds__(256) void rope_conv(const float* __restrict__ qkv,
                                                 const float* __restrict__ cos_t,
                                                 const float* __restrict__ sin_t,
                                                 __half* __restrict__ qf,
                                                 __half* __restrict__ kf,
                                                 __half* __restrict__ vf)
{
    int idx = blockIdx.x * blockDim.x + threadIdx.x;  // bt*48*32
    int d5   = idx & 31;
    int rest = idx >> 5;
    int head = rest % 48;
    int bt   = rest / 48;
    int t = bt & (TT - 1);
    int b = bt >> 11;
    size_t src = ((size_t)bt * 48 + head) * 64;
    float x1 = qkv[src + d5];
    float x2 = qkv[src + 32 + d5];

    if (head < 32) {
        float c = cos_t[t * 64 + d5];
        float s = sin_t[t * 64 + d5];
        float y1 = x1 * c - x2 * s;
        float y2 = x2 * c + x1 * s;
        if (head < NH) {
            y1 *= 0.125f; y2 *= 0.125f;
            size_t dst = (((size_t)(b * NH + head)) * TT + t) * 64;
            qf[dst + d5]      = __float2half_rn(y1);
            qf[dst + 32 + d5] = __float2half_rn(y2);
        } else {
            size_t dst = (((size_t)(b * NH + head - NH)) * TT + t) * 64;
            kf[dst + d5]      = __float2half_rn(y1);
            kf[dst + 32 + d5] = __float2half_rn(y2);
        }
    } else {
        size_t dst = (((size_t)(b * NH + head - 32)) * TT + t) * 64;
        vf[dst + d5]      = __float2half_rn(x1);
        vf[dst + 32 + d5] = __float2half_rn(x2);
    }
}

// ===========================================================================
// fp16x1 HMMA GEMM, 4-stage cp.async pipeline: C[.., ldc] = A[M,K]*B[N,K]^T
// 128x128 CTA tile, BK=32, 8 warps (64x32 each), 3 chunks in flight.
// ===========================================================================
#define SA 40
#define TSB (128 * SA * 2)        // one operand tile (10240 B)
#define STGB (2 * TSB)            // per-stage: A + B (20480 B)
#define NSTG 4                    // 80 KB total

__global__ __launch_bounds__(256) void gemm_f16p4(const __half* __restrict__ A,
                                                  const __half* __restrict__ Bm,
                                                  float* __restrict__ C,
                                                  int ldc, int K)
{
    extern __shared__ char dsm[];
    const uint32_t sbase = smem_to_u32(dsm);

    const int tid  = threadIdx.x;
    const int wid  = tid >> 5;
    const int lane = tid & 31;
    const int warp_m = wid >> 2;
    const int warp_n = wid & 3;
    const int bm = blockIdx.y * 128;
    const int bn = blockIdx.x * 128;
    const int lj = lane & 7;
    const int li = lane >> 3;

    float c[4][4][4];
#pragma unroll
    for (int mt = 0; mt < 4; mt++)
#pragma unroll
        for (int nt = 0; nt < 4; nt++)
#pragma unroll
            for (int j = 0; j < 4; j++) c[mt][nt][j] = 0.f;

    const int a_row_base = warp_m * 64 + lj + ((li & 1) << 3);
    const int a_col_base = (li >> 1) << 3;
    const int b_row = warp_n * 32 + li * 8 + lj;

    auto load_chunk = [&](int ch, int stg) {
#pragma unroll
        for (int i = 0; i < 4; i++) {
            const int tile = i >> 1;
            const int v = ((i & 1) << 8) + tid;
            const int r = v >> 2;
            const int c8 = (v & 3) << 3;
            const __half* sp = (tile == 0) ? A : Bm;
            const int grow = ((tile == 0) ? bm : bn) + r;
            uint32_t dst = sbase + stg * STGB + tile * TSB + (uint32_t)(r * SA + c8) * 2;
            CP_ASYNC16(dst, sp + (size_t)grow * K + ch * 32 + c8);
        }
        CP_COMMIT();
    };

    const int nchunks = K >> 5;
    // prologue: fill 3 stages
    load_chunk(0, 0);
    load_chunk(1, 1);
    load_chunk(2, 2);

    for (int ch = 0; ch < nchunks; ch++) {
        const int rem = nchunks - 1 - ch;       // chunks after ch
        if (rem >= 2)      { CP_WAITG(2); }     // {ch+1, ch+2} may stay in flight
        else if (rem == 1) { CP_WAITG(1); }
        else               { CP_WAITG(0); }
        __syncthreads();                        // all warps done with stage being overwritten
        if (ch + 3 < nchunks) load_chunk(ch + 3, (ch + 3) & 3);

        const uint32_t base = sbase + (ch & 3) * STGB;
        const uint32_t oB = TSB;
#pragma unroll
        for (int ks = 0; ks < 2; ks++) {
            const int k0 = ks * 16;
            unsigned bh[2][4];
#pragma unroll
            for (int kh = 0; kh < 2; kh++) {
                uint32_t ba = base + oB + (uint32_t)(b_row * SA + k0 + kh * 8) * 2;
                ldsm4(bh[kh], ba);
            }
#pragma unroll
            for (int mt = 0; mt < 4; mt++) {
                unsigned a[4];
                uint32_t aa = base + (uint32_t)((a_row_base + mt * 16) * SA + k0 + a_col_base) * 2;
                ldsm4(a, aa);
#pragma unroll
                for (int nt = 0; nt < 4; nt++)
                    mma_f16(c[mt][nt], a, bh[0][nt], bh[1][nt]);
            }
        }
    }

    const int q  = lane >> 2;
    const int t4 = lane & 3;
#pragma unroll
    for (int mt = 0; mt < 4; mt++) {
        int row0 = bm + warp_m * 64 + mt * 16 + q;
#pragma unroll
        for (int nt = 0; nt < 4; nt++) {
            int col = bn + warp_n * 32 + nt * 8 + 2 * t4;
            *(float2*)&C[(size_t)row0 * ldc + col] =
                make_float2(c[mt][nt][0], c[mt][nt][1]);
            *(float2*)&C[(size_t)(row0 + 8) * ldc + col] =
                make_float2(c[mt][nt][2], c[mt][nt][3]);
        }
    }
}

// ===========================================================================
// fp16x1 HMMA flash attention (round-11, proven), double-buffered K/V.
// ===========================================================================
#define FSA 72
#define FT (64 * FSA)

__global__ __launch_bounds__(128) void flash_attn_f16(const __half* __restrict__ Qf,
                                                      const __half* __restrict__ Kf,
                                                      const __half* __restrict__ Vf,
                                                      __half* __restrict__ ctx)
{
    __shared__ __half sm_[5 * FT];
    const uint32_t sbase = smem_to_u32(sm_);

    const int qt = blockIdx.x;
    const int h  = blockIdx.y;
    const int b  = blockIdx.z;
    const int tid  = threadIdx.x;
    const int wid  = tid >> 5;
    const int lane = tid & 31;
    const int lj = lane & 7;
    const int li = lane >> 3;
    const int g  = lane >> 2;
    const int t4 = lane & 3;
    const int wrow = wid * 16;

    const size_t headbase = ((size_t)(b * NH + h)) * TT * 64;

    auto load_kv = [&](int kt, int buf) {
#pragma unroll
        for (int i = 0; i < 8; i++) {
            int v = i * 128 + tid;
            int tile = v >> 9;
            int r = (v >> 3) & 63;
            int c8 = (v & 7) << 3;
            const __half* sp = tile ? Vf : Kf;
            uint32_t dst = sbase + (uint32_t)(FT * 2) * (1 + 2 * buf + tile)
                         + (uint32_t)(r * FSA + c8) * 2;
            CP_ASYNC16(dst, sp + headbase + (size_t)(kt * 64 + r) * 64 + c8);
        }
        CP_COMMIT();
    };

#pragma unroll
    for (int i = 0; i < 4; i++) {
        int v = i * 128 + tid;
        int r = v >> 3;
        int c8 = (v & 7) << 3;
        uint32_t dst = sbase + (uint32_t)(r * FSA + c8) * 2;
        CP_ASYNC16(dst, Qf + headbase + (size_t)(qt * 64 + r) * 64 + c8);
    }
    load_kv(0, 0);

    float m0 = -1e30f, m1 = -1e30f, l0 = 0.f, l1 = 0.f;
    float o[8][4];
#pragma unroll
    for (int nt = 0; nt < 8; nt++)
#pragma unroll
        for (int j = 0; j < 4; j++) o[nt][j] = 0.f;

    const int a_row = wrow + lj + ((li & 1) << 3);
    const int a_col = (li >> 1) << 3;
    const int b_row = li * 8 + lj;
    const int v_row = lj + ((li & 1) << 3);
    const int v_col = (lane >> 4) << 3;

    for (int kt = 0; kt <= qt; kt++) {
        const int buf = kt & 1;
        const bool pf = (kt + 1 <= qt);
        if (pf) load_kv(kt + 1, buf ^ 1);
        if (pf) { CP_WAITG(1); } else { CP_WAITG(0); }
        __syncthreads();

        const uint32_t oK = (uint32_t)(FT * 2) * (1 + 2 * buf);
        const uint32_t oV = oK + (uint32_t)(FT * 2);

        float s[8][4];
#pragma unroll
        for (int nt = 0; nt < 8; nt++)
#pragma unroll
            for (int j = 0; j < 4; j++) s[nt][j] = 0.f;

#pragma unroll
        for (int ks = 0; ks < 4; ks++) {
            const int k0 = ks * 16;
            unsigned a[4];
            uint32_t aa = sbase + (uint32_t)(a_row * FSA + k0 + a_col) * 2;
            ldsm4(a, aa);
#pragma unroll
            for (int nh = 0; nh < 2; nh++) {
                unsigned kfr[2][4];
#pragma unroll
                for (int kh = 0; kh < 2; kh++) {
                    uint32_t ba = sbase + oK + (uint32_t)((b_row + nh * 32) * FSA + k0 + kh * 8) * 2;
                    ldsm4(kfr[kh], ba);
                }
#pragma unroll
                for (int nt = 0; nt < 4; nt++)
                    mma_f16(s[nh * 4 + nt], a, kfr[0][nt], kfr[1][nt]);
            }
        }

        if (kt == qt) {
            int r0 = wrow + g, r1 = r0 + 8;
#pragma unroll
            for (int nt = 0; nt < 8; nt++) {
                int c0 = nt * 8 + 2 * t4, c1 = c0 + 1;
                if (c0 > r0) s[nt][0] = -1e30f;
                if (c1 > r0) s[nt][1] = -1e30f;
                if (c0 > r1) s[nt][2] = -1e30f;
                if (c1 > r1) s[nt][3] = -1e30f;
            }
        }

        float mx0 = -1e30f, mx1 = -1e30f;
#pragma unroll
        for (int nt = 0; nt < 8; nt++) {
            mx0 = fmaxf(mx0, fmaxf(s[nt][0], s[nt][1]));
            mx1 = fmaxf(mx1, fmaxf(s[nt][2], s[nt][3]));
        }
        mx0 = fmaxf(mx0, __shfl_xor_sync(0xffffffffu, mx0, 1));
        mx0 = fmaxf(mx0, __shfl_xor_sync(0xffffffffu, mx0, 2));
        mx1 = fmaxf(mx1, __shfl_xor_sync(0xffffffffu, mx1, 1));
        mx1 = fmaxf(mx1, __shfl_xor_sync(0xffffffffu, mx1, 2));

        float mn0 = fmaxf(m0, mx0), mn1 = fmaxf(m1, mx1);
        float alpha0 = __expf(m0 - mn0), alpha1 = __expf(m1 - mn1);
        m0 = mn0; m1 = mn1;

        float sum0 = 0.f, sum1 = 0.f;
#pragma unroll
        for (int nt = 0; nt < 8; nt++) {
            s[nt][0] = __expf(s[nt][0] - mn0);
            s[nt][1] = __expf(s[nt][1] - mn0);
            s[nt][2] = __expf(s[nt][2] - mn1);
            s[nt][3] = __expf(s[nt][3] - mn1);
            sum0 += s[nt][0] + s[nt][1];
            sum1 += s[nt][2] + s[nt][3];
        }
        sum0 += __shfl_xor_sync(0xffffffffu, sum0, 1);
        sum0 += __shfl_xor_sync(0xffffffffu, sum0, 2);
        sum1 += __shfl_xor_sync(0xffffffffu, sum1, 1);
        sum1 += __shfl_xor_sync(0xffffffffu, sum1, 2);
        l0 = l0 * alpha0 + sum0;
        l1 = l1 * alpha1 + sum1;

#pragma unroll
        for (int nt = 0; nt < 8; nt++) {
            o[nt][0] *= alpha0; o[nt][1] *= alpha0;
            o[nt][2] *= alpha1; o[nt][3] *= alpha1;
        }

#pragma unroll
        for (int ks = 0; ks < 4; ks++) {
            const int k0 = ks * 16;
            unsigned a[4];
            {
                float* p0 = s[2 * ks];
                float* p1 = s[2 * ks + 1];
                a[0] = pkH(p0[0], p0[1]);
                a[1] = pkH(p0[2], p0[3]);
                a[2] = pkH(p1[0], p1[1]);
                a[3] = pkH(p1[2], p1[3]);
            }
#pragma unroll
            for (int nh = 0; nh < 4; nh++) {
                uint32_t va = sbase + oV + (uint32_t)((k0 + v_row) * FSA + nh * 16 + v_col) * 2;
                unsigned vfr[4];
                ldsm4t(vfr, va);
                mma_f16(o[nh * 2],     a, vfr[0], vfr[1]);
                mma_f16(o[nh * 2 + 1], a, vfr[2], vfr[3]);
            }
        }
        __syncthreads();
    }

    float inv0 = 1.f / l0, inv1 = 1.f / l1;
    int row0 = qt * 64 + wrow + g;
    size_t base0 = ((size_t)(b * TT + row0)) * HIDDEN + h * 64;
    size_t base1 = base0 + 8 * HIDDEN;
#pragma unroll
    for (int nt = 0; nt < 8; nt++) {
        int c = nt * 8 + 2 * t4;
        __half2 p0 = __floats2half2_rn(o[nt][0] * inv0, o[nt][1] * inv0);
        __half2 p1 = __floats2half2_rn(o[nt][2] * inv1, o[nt][3] * inv1);
        *(unsigned*)&ctx[base0 + c] = *(unsigned*)&p0;
        *(unsigned*)&ctx[base1 + c] = *(unsigned*)&p1;
    }
}

// ---------------------------------------------------------------------------
extern "C" void kernel_launch(void* const* d_in, const int* in_sizes, int n_in,
                              void* d_out, int out_size)
{
    const float* hs    = (const float*)d_in[0];
    const float* cos_t = (const float*)d_in[1];
    const float* sin_t = (const float*)d_in[2];
    const float* wqkv  = (const float*)d_in[3];
    const float* wo    = (const float*)d_in[4];
    float* out = (float*)d_out;

    float* qkv = nullptr;
    __half *hs_f, *wq_h, *wo_h, *ctx, *qf, *kf, *vf;
    cudaGetSymbolAddress((void**)&qkv,  g_qkv);
    cudaGetSymbolAddress((void**)&hs_f, g_hs_f);
    cudaGetSymbolAddress((void**)&wq_h, g_wq_h);
    cudaGetSymbolAddress((void**)&wo_h, g_wo_h);
    cudaGetSymbolAddress((void**)&ctx,  g_ctx);
    cudaGetSymbolAddress((void**)&qf,   g_qf);
    cudaGetSymbolAddress((void**)&kf,   g_kf);
    cudaGetSymbolAddress((void**)&vf,   g_vf);

    // 0) converts (all plain fp16)
    conv_f16<<<MROWS * HIDDEN / 4 / 256, 256>>>(hs, hs_f, MROWS * HIDDEN / 4);
    conv_f16<<<QKV_O * HIDDEN / 4 / 256, 256>>>(wqkv, wq_h, QKV_O * HIDDEN / 4);
    conv_f16<<<HIDDEN * HIDDEN / 4 / 256, 256>>>(wo, wo_h, HIDDEN * HIDDEN / 4);

    const int gsm = NSTG * STGB;  // 80 KB
    cudaFuncSetAttribute(gemm_f16p4, cudaFuncAttributeMaxDynamicSharedMemorySize, gsm);

    // 1) QKV = hs @ wqkv^T  (single x1 GEMM, N=3072)
    gemm_f16p4<<<dim3(QKV_O / 128, MROWS / 128), 256, gsm>>>(
        hs_f, wq_h, qkv, QKV_O, HIDDEN);

    // 2) Fused RoPE + fp16 head-major layout
    rope_conv<<<(MROWS * 48 * 32) / 256, 256>>>(qkv, cos_t, sin_t, qf, kf, vf);

    // 3) Flash attention (fp16 x1 HMMA, double-buffered K/V)
    flash_attn_f16<<<dim3(TT / 64, NH, BB), 128>>>(qf, kf, vf, ctx);

    // 4) out = ctx @ wo^T (x1 weights)
    gemm_f16p4<<<dim3(HIDDEN / 128, MROWS / 128), 256, gsm>>>(
        ctx, wo_h, out, HIDDEN, HIDDEN);
}

// round 16
// speedup vs baseline: 1.0222x; 1.0222x over previous
#include <cuda_runtime.h>
#include <cuda_bf16.h>
#include <cuda_fp16.h>
#include <cstdint>
#include <math.h>

#define BB 2
#define TT 2048
#define HIDDEN 1024
#define NH 16
#define QKV_O 3072   // (16 + 2*16) * 64
#define MROWS (BB*TT) // 4096

// Scratch (allocation-free rule: __device__ globals)
__device__ __half g_hs_f[(size_t)MROWS * HIDDEN];
__device__ __half g_wq_h[(size_t)QKV_O * HIDDEN];
__device__ __half g_wo_h[(size_t)HIDDEN * HIDDEN];
__device__ __half g_ctx[(size_t)MROWS * HIDDEN];
// head-major fp16 attention operands: [b, h, t, d]
__device__ __half g_qf[(size_t)BB * NH * TT * 64];
__device__ __half g_kf[(size_t)BB * NH * TT * 64];
__device__ __half g_vf[(size_t)BB * NH * TT * 64];

// ===========================================================================
// Helpers
// ===========================================================================
__device__ __forceinline__ uint32_t smem_to_u32(const void* p) {
    uint32_t a;
    asm("{ .reg .u64 t; cvta.to.shared.u64 t, %1; cvt.u32.u64 %0, t; }" : "=r"(a) : "l"(p));
    return a;
}
__device__ __forceinline__ void ldsm4(unsigned* r, uint32_t addr) {
    asm volatile("ldmatrix.sync.aligned.m8n8.x4.shared.b16 {%0,%1,%2,%3}, [%4];"
                 : "=r"(r[0]), "=r"(r[1]), "=r"(r[2]), "=r"(r[3]) : "r"(addr));
}
__device__ __forceinline__ void ldsm4t(unsigned* r, uint32_t addr) {
    asm volatile("ldmatrix.sync.aligned.m8n8.x4.trans.shared.b16 {%0,%1,%2,%3}, [%4];"
                 : "=r"(r[0]), "=r"(r[1]), "=r"(r[2]), "=r"(r[3]) : "r"(addr));
}
__device__ __forceinline__ void mma_f16(float* c, const unsigned* a, unsigned b0, unsigned b1) {
    asm volatile("mma.sync.aligned.m16n8k16.row.col.f32.f16.f16.f32 "
                 "{%0,%1,%2,%3}, {%4,%5,%6,%7}, {%8,%9}, {%0,%1,%2,%3};"
                 : "+f"(c[0]), "+f"(c[1]), "+f"(c[2]), "+f"(c[3])
                 : "r"(a[0]), "r"(a[1]), "r"(a[2]), "r"(a[3]), "r"(b0), "r"(b1));
}
__device__ __forceinline__ unsigned pkH(float x, float y) {
    __half2 p(__float2half_rn(x), __float2half_rn(y));
    return *(unsigned*)&p;
}
#define CP_ASYNC16(dst, src) \
    asm volatile("cp.async.cg.shared.global [%0], [%1], 16;" :: "r"(dst), "l"(src))
#define CP_COMMIT() asm volatile("cp.async.commit_group;" ::: "memory")
#define CP_WAITG(n) asm volatile("cp.async.wait_group %0;" :: "n"(n) : "memory")

// ===========================================================================
// Converter (fp32 -> fp16)
// ===========================================================================
__global__ __launch_bounds__(256) void conv_f16(const float* __restrict__ x,
                                                __half* __restrict__ h, int n4)
{
    int i = blockIdx.x * blockDim.x + threadIdx.x;
    if (i >= n4) return;
    float4 v = ((const float4*)x)[i];
    __half2 p0 = __floats2half2_rn(v.x, v.y);
    __half2 p1 = __floats2half2_rn(v.z, v.w);
    uint2 o; o.x = *(uint32_t*)&p0; o.y = *(uint32_t*)&p1;
    ((uint2*)h)[i] = o;
}

// ===========================================================================
// QKV GEMM fused with RoPE + head-major fp16 output.
// C-tile = [128 rows(bt), 128 cols] = 2 heads. Mainloop = 4-stage cp.async
// fp16x1 HMMA (round-14 structure). Epilogue stages fp32 tile in smem,
// applies RoPE to (d, d+32) pairs, writes qf/kf/vf directly.
// ===========================================================================
#define SA 40
#define TSB (128 * SA * 2)        // one operand tile (10240 B)
#define STGB (2 * TSB)            // per-stage: A + B (20480 B)
#define NSTG 4                    // 80 KB total
#define CLD 132                   // fp32 staging stride

__global__ __launch_bounds__(256) void gemm_qkv_rope(const __half* __restrict__ A,
                                                     const __half* __restrict__ Bm,
                                                     const float* __restrict__ cos_t,
                                                     const float* __restrict__ sin_t,
                                                     __half* __restrict__ qf,
                                                     __half* __restrict__ kf,
                                                     __half* __restrict__ vf)
{
    extern __shared__ char dsm[];
    const uint32_t sbase = smem_to_u32(dsm);
    const int K = HIDDEN;

    const int tid  = threadIdx.x;
    const int wid  = tid >> 5;
    const int lane = tid & 31;
    const int warp_m = wid >> 2;
    const int warp_n = wid & 3;
    const int bm = blockIdx.y * 128;
    const int bn = blockIdx.x * 128;
    const int lj = lane & 7;
    const int li = lane >> 3;

    float c[4][4][4];
#pragma unroll
    for (int mt = 0; mt < 4; mt++)
#pragma unroll
        for (int nt = 0; nt < 4; nt++)
#pragma unroll
            for (int j = 0; j < 4; j++) c[mt][nt][j] = 0.f;

    const int a_row_base = warp_m * 64 + lj + ((li & 1) << 3);
    const int a_col_base = (li >> 1) << 3;
    const int b_row = warp_n * 32 + li * 8 + lj;

    auto load_chunk = [&](int ch, int stg) {
#pragma unroll
        for (int i = 0; i < 4; i++) {
            const int tile = i >> 1;
            const int v = ((i & 1) << 8) + tid;
            const int r = v >> 2;
            const int c8 = (v & 3) << 3;
            const __half* sp = (tile == 0) ? A : Bm;
            const int grow = ((tile == 0) ? bm : bn) + r;
            uint32_t dst = sbase + stg * STGB + tile * TSB + (uint32_t)(r * SA + c8) * 2;
            CP_ASYNC16(dst, sp + (size_t)grow * K + ch * 32 + c8);
        }
        CP_COMMIT();
    };

    const int nchunks = K >> 5;
    load_chunk(0, 0);
    load_chunk(1, 1);
    load_chunk(2, 2);

    for (int ch = 0; ch < nchunks; ch++) {
        const int rem = nchunks - 1 - ch;
        if (rem >= 2)      { CP_WAITG(2); }
        else if (rem == 1) { CP_WAITG(1); }
        else               { CP_WAITG(0); }
        __syncthreads();
        if (ch + 3 < nchunks) load_chunk(ch + 3, (ch + 3) & 3);

        const uint32_t base = sbase + (ch & 3) * STGB;
        const uint32_t oB = TSB;
#pragma unroll
        for (int ks = 0; ks < 2; ks++) {
            const int k0 = ks * 16;
            unsigned bh[2][4];
#pragma unroll
            for (int kh = 0; kh < 2; kh++) {
                uint32_t ba = base + oB + (uint32_t)(b_row * SA + k0 + kh * 8) * 2;
                ldsm4(bh[kh], ba);
            }
#pragma unroll
            for (int mt = 0; mt < 4; mt++) {
                unsigned a[4];
                uint32_t aa = base + (uint32_t)((a_row_base + mt * 16) * SA + k0 + a_col_base) * 2;
                ldsm4(a, aa);
#pragma unroll
                for (int nt = 0; nt < 4; nt++)
                    mma_f16(c[mt][nt], a, bh[0][nt], bh[1][nt]);
            }
        }
    }

    // ---- epilogue: stage fp32 tile in smem ----
    __syncthreads();                       // all warps done with pipeline smem
    float* smc = (float*)dsm;              // 128 x CLD fp32 (67.6 KB <= 80 KB)
    const int q  = lane >> 2;
    const int t4 = lane & 3;
#pragma unroll
    for (int mt = 0; mt < 4; mt++) {
        int r0 = warp_m * 64 + mt * 16 + q;
#pragma unroll
        for (int nt = 0; nt < 4; nt++) {
            int col = warp_n * 32 + nt * 8 + 2 * t4;
            *(float2*)&smc[r0 * CLD + col] = make_float2(c[mt][nt][0], c[mt][nt][1]);
            *(float2*)&smc[(r0 + 8) * CLD + col] = make_float2(c[mt][nt][2], c[mt][nt][3]);
        }
    }
    __syncthreads();

    // ---- RoPE + head-major fp16 writes: 8192 (r, d)-pairs, 32/thread ----
    const int ghead0 = bn >> 6;            // first head in this tile (2 heads)
#pragma unroll
    for (int i = 0; i < 32; i++) {
        int e = i * 256 + tid;             // 0..8191
        int r  = e >> 6;
        int hh = (e >> 5) & 1;
        int d  = e & 31;
        float x1 = smc[r * CLD + hh * 64 + d];
        float x2 = smc[r * CLD + hh * 64 + d + 32];
        int bt = bm + r;
        int t = bt & (TT - 1);
        int b = bt >> 11;
        int gh = ghead0 + hh;
        if (gh < 32) {                     // Q or K: RoPE
            float cc = cos_t[t * 64 + d];
            float ss = sin_t[t * 64 + d];
            float y1 = x1 * cc - x2 * ss;
            float y2 = x2 * cc + x1 * ss;
            if (gh < NH) {
                y1 *= 0.125f; y2 *= 0.125f;
                size_t dst = (((size_t)(b * NH + gh)) * TT + t) * 64 + d;
                qf[dst]      = __float2half_rn(y1);
                qf[dst + 32] = __float2half_rn(y2);
            } else {
                size_t dst = (((size_t)(b * NH + gh - NH)) * TT + t) * 64 + d;
                kf[dst]      = __float2half_rn(y1);
                kf[dst + 32] = __float2half_rn(y2);
            }
        } else {                           // V
            size_t dst = (((size_t)(b * NH + gh - 32)) * TT + t) * 64 + d;
            vf[dst]      = __float2half_rn(x1);
            vf[dst + 32] = __float2half_rn(x2);
        }
    }
}

// ===========================================================================
// fp16x1 HMMA GEMM (4-stage, round-14): C[.., ldc] = A[M,K]*B[N,K]^T
// Used for the O-projection.
// ===========================================================================
__global__ __launch_bounds__(256) void gemm_f16p4(const __half* __restrict__ A,
                                                  const __half* __restrict__ Bm,
                                                  float* __restrict__ C,
                                                  int ldc, int K)
{
    extern __shared__ char dsm[];
    const uint32_t sbase = smem_to_u32(dsm);

    const int tid  = threadIdx.x;
    const int wid  = tid >> 5;
    const int lane = tid & 31;
    const int warp_m = wid >> 2;
    const int warp_n = wid & 3;
    const int bm = blockIdx.y * 128;
    const int bn = blockIdx.x * 128;
    const int lj = lane & 7;
    const int li = lane >> 3;

    float c[4][4][4];
#pragma unroll
    for (int mt = 0; mt < 4; mt++)
#pragma unroll
        for (int nt = 0; nt < 4; nt++)
#pragma unroll
            for (int j = 0; j < 4; j++) c[mt][nt][j] = 0.f;

    const int a_row_base = warp_m * 64 + lj + ((li & 1) << 3);
    const int a_col_base = (li >> 1) << 3;
    const int b_row = warp_n * 32 + li * 8 + lj;

    auto load_chunk = [&](int ch, int stg) {
#pragma unroll
        for (int i = 0; i < 4; i++) {
            const int tile = i >> 1;
            const int v = ((i & 1) << 8) + tid;
            const int r = v >> 2;
            const int c8 = (v & 3) << 3;
            const __half* sp = (tile == 0) ? A : Bm;
            const int grow = ((tile == 0) ? bm : bn) + r;
            uint32_t dst = sbase + stg * STGB + tile * TSB + (uint32_t)(r * SA + c8) * 2;
            CP_ASYNC16(dst, sp + (size_t)grow * K + ch * 32 + c8);
        }
        CP_COMMIT();
    };

    const int nchunks = K >> 5;
    load_chunk(0, 0);
    load_chunk(1, 1);
    load_chunk(2, 2);

    for (int ch = 0; ch < nchunks; ch++) {
        const int rem = nchunks - 1 - ch;
        if (rem >= 2)      { CP_WAITG(2); }
        else if (rem == 1) { CP_WAITG(1); }
        else               { CP_WAITG(0); }
        __syncthreads();
        if (ch + 3 < nchunks) load_chunk(ch + 3, (ch + 3) & 3);

        const uint32_t base = sbase + (ch & 3) * STGB;
        const uint32_t oB = TSB;
#pragma unroll
        for (int ks = 0; ks < 2; ks++) {
            const int k0 = ks * 16;
            unsigned bh[2][4];
#pragma unroll
            for (int kh = 0; kh < 2; kh++) {
                uint32_t ba = base + oB + (uint32_t)(b_row * SA + k0 + kh * 8) * 2;
                ldsm4(bh[kh], ba);
            }
#pragma unroll
            for (int mt = 0; mt < 4; mt++) {
                unsigned a[4];
                uint32_t aa = base + (uint32_t)((a_row_base + mt * 16) * SA + k0 + a_col_base) * 2;
                ldsm4(a, aa);
#pragma unroll
                for (int nt = 0; nt < 4; nt++)
                    mma_f16(c[mt][nt], a, bh[0][nt], bh[1][nt]);
            }
        }
    }

    const int q  = lane >> 2;
    const int t4 = lane & 3;
#pragma unroll
    for (int mt = 0; mt < 4; mt++) {
        int row0 = bm + warp_m * 64 + mt * 16 + q;
#pragma unroll
        for (int nt = 0; nt < 4; nt++) {
            int col = bn + warp_n * 32 + nt * 8 + 2 * t4;
            *(float2*)&C[(size_t)row0 * ldc + col] =
                make_float2(c[mt][nt][0], c[mt][nt][1]);
            *(float2*)&C[(size_t)(row0 + 8) * ldc + col] =
                make_float2(c[mt][nt][2], c[mt][nt][3]);
        }
    }
}

// ===========================================================================
// fp16x1 HMMA flash attention (round-11, proven), double-buffered K/V.
// qt reversed: largest causal workload scheduled first.
// ===========================================================================
#define FSA 72
#define FT (64 * FSA)

__global__ __launch_bounds__(128) void flash_attn_f16(const __half* __restrict__ Qf,
                                                      const __half* __restrict__ Kf,
                                                      const __half* __restrict__ Vf,
                                                      __half* __restrict__ ctx)
{
    __shared__ __half sm_[5 * FT];
    const uint32_t sbase = smem_to_u32(sm_);

    const int qt = gridDim.x - 1 - blockIdx.x;   // big tiles first
    const int h  = blockIdx.y;
    const int b  = blockIdx.z;
    const int tid  = threadIdx.x;
    const int wid  = tid >> 5;
    const int lane = tid & 31;
    const int lj = lane & 7;
    const int li = lane >> 3;
    const int g  = lane >> 2;
    const int t4 = lane & 3;
    const int wrow = wid * 16;

    const size_t headbase = ((size_t)(b * NH + h)) * TT * 64;

    auto load_kv = [&](int kt, int buf) {
#pragma unroll
        for (int i = 0; i < 8; i++) {
            int v = i * 128 + tid;
            int tile = v >> 9;
            int r = (v >> 3) & 63;
            int c8 = (v & 7) << 3;
            const __half* sp = tile ? Vf : Kf;
            uint32_t dst = sbase + (uint32_t)(FT * 2) * (1 + 2 * buf + tile)
                         + (uint32_t)(r * FSA + c8) * 2;
            CP_ASYNC16(dst, sp + headbase + (size_t)(kt * 64 + r) * 64 + c8);
        }
        CP_COMMIT();
    };

#pragma unroll
    for (int i = 0; i < 4; i++) {
        int v = i * 128 + tid;
        int r = v >> 3;
        int c8 = (v & 7) << 3;
        uint32_t dst = sbase + (uint32_t)(r * FSA + c8) * 2;
        CP_ASYNC16(dst, Qf + headbase + (size_t)(qt * 64 + r) * 64 + c8);
    }
    load_kv(0, 0);

    float m0 = -1e30f, m1 = -1e30f, l0 = 0.f, l1 = 0.f;
    float o[8][4];
#pragma unroll
    for (int nt = 0; nt < 8; nt++)
#pragma unroll
        for (int j = 0; j < 4; j++) o[nt][j] = 0.f;

    const int a_row = wrow + lj + ((li & 1) << 3);
    const int a_col = (li >> 1) << 3;
    const int b_row = li * 8 + lj;
    const int v_row = lj + ((li & 1) << 3);
    const int v_col = (lane >> 4) << 3;

    for (int kt = 0; kt <= qt; kt++) {
        const int buf = kt & 1;
        const bool pf = (kt + 1 <= qt);
        if (pf) load_kv(kt + 1, buf ^ 1);
        if (pf) { CP_WAITG(1); } else { CP_WAITG(0); }
        __syncthreads();

        const uint32_t oK = (uint32_t)(FT * 2) * (1 + 2 * buf);
        const uint32_t oV = oK + (uint32_t)(FT * 2);

        float s[8][4];
#pragma unroll
        for (int nt = 0; nt < 8; nt++)
#pragma unroll
            for (int j = 0; j < 4; j++) s[nt][j] = 0.f;

#pragma unroll
        for (int ks = 0; ks < 4; ks++) {
            const int k0 = ks * 16;
            unsigned a[4];
            uint32_t aa = sbase + (uint32_t)(a_row * FSA + k0 + a_col) * 2;
            ldsm4(a, aa);
#pragma unroll
            for (int nh = 0; nh < 2; nh++) {
                unsigned kfr[2][4];
#pragma unroll
                for (int kh = 0; kh < 2; kh++) {
                    uint32_t ba = sbase + oK + (uint32_t)((b_row + nh * 32) * FSA + k0 + kh * 8) * 2;
                    ldsm4(kfr[kh], ba);
                }
#pragma unroll
                for (int nt = 0; nt < 4; nt++)
                    mma_f16(s[nh * 4 + nt], a, kfr[0][nt], kfr[1][nt]);
            }
        }

        if (kt == qt) {
            int r0 = wrow + g, r1 = r0 + 8;
#pragma unroll
            for (int nt = 0; nt < 8; nt++) {
                int c0 = nt * 8 + 2 * t4, c1 = c0 + 1;
                if (c0 > r0) s[nt][0] = -1e30f;
                if (c1 > r0) s[nt][1] = -1e30f;
                if (c0 > r1) s[nt][2] = -1e30f;
                if (c1 > r1) s[nt][3] = -1e30f;
            }
        }

        float mx0 = -1e30f, mx1 = -1e30f;
#pragma unroll
        for (int nt = 0; nt < 8; nt++) {
            mx0 = fmaxf(mx0, fmaxf(s[nt][0], s[nt][1]));
            mx1 = fmaxf(mx1, fmaxf(s[nt][2], s[nt][3]));
        }
        mx0 = fmaxf(mx0, __shfl_xor_sync(0xffffffffu, mx0, 1));
        mx0 = fmaxf(mx0, __shfl_xor_sync(0xffffffffu, mx0, 2));
        mx1 = fmaxf(mx1, __shfl_xor_sync(0xffffffffu, mx1, 1));
        mx1 = fmaxf(mx1, __shfl_xor_sync(0xffffffffu, mx1, 2));

        float mn0 = fmaxf(m0, mx0), mn1 = fmaxf(m1, mx1);
        float alpha0 = __expf(m0 - mn0), alpha1 = __expf(m1 - mn1);
        m0 = mn0; m1 = mn1;

        float sum0 = 0.f, sum1 = 0.f;
#pragma unroll
        for (int nt = 0; nt < 8; nt++) {
            s[nt][0] = __expf(s[nt][0] - mn0);
            s[nt][1] = __expf(s[nt][1] - mn0);
            s[nt][2] = __expf(s[nt][2] - mn1);
            s[nt][3] = __expf(s[nt][3] - mn1);
            sum0 += s[nt][0] + s[nt][1];
            sum1 += s[nt][2] + s[nt][3];
        }
        sum0 += __shfl_xor_sync(0xffffffffu, sum0, 1);
        sum0 += __shfl_xor_sync(0xffffffffu, sum0, 2);
        sum1 += __shfl_xor_sync(0xffffffffu, sum1, 1);
        sum1 += __shfl_xor_sync(0xffffffffu, sum1, 2);
        l0 = l0 * alpha0 + sum0;
        l1 = l1 * alpha1 + sum1;

#pragma unroll
        for (int nt = 0; nt < 8; nt++) {
            o[nt][0] *= alpha0; o[nt][1] *= alpha0;
            o[nt][2] *= alpha1; o[nt][3] *= alpha1;
        }

#pragma unroll
        for (int ks = 0; ks < 4; ks++) {
            const int k0 = ks * 16;
            unsigned a[4];
            {
                float* p0 = s[2 * ks];
                float* p1 = s[2 * ks + 1];
                a[0] = pkH(p0[0], p0[1]);
                a[1] = pkH(p0[2], p0[3]);
                a[2] = pkH(p1[0], p1[1]);
                a[3] = pkH(p1[2], p1[3]);
            }
#pragma unroll
            for (int nh = 0; nh < 4; nh++) {
                uint32_t va = sbase + oV + (uint32_t)((k0 + v_row) * FSA + nh * 16 + v_col) * 2;
                unsigned vfr[4];
                ldsm4t(vfr, va);
                mma_f16(o[nh * 2],     a, vfr[0], vfr[1]);
                mma_f16(o[nh * 2 + 1], a, vfr[2], vfr[3]);
            }
        }
        __syncthreads();
    }

    float inv0 = 1.f / l0, inv1 = 1.f / l1;
    int row0 = qt * 64 + wrow + g;
    size_t base0 = ((size_t)(b * TT + row0)) * HIDDEN + h * 64;
    size_t base1 = base0 + 8 * HIDDEN;
#pragma unroll
    for (int nt = 0; nt < 8; nt++) {
        int c = nt * 8 + 2 * t4;
        __half2 p0 = __floats2half2_rn(o[nt][0] * inv0, o[nt][1] * inv0);
        __half2 p1 = __floats2half2_rn(o[nt][2] * inv1, o[nt][3] * inv1);
        *(unsigned*)&ctx[base0 + c] = *(unsigned*)&p0;
        *(unsigned*)&ctx[base1 + c] = *(unsigned*)&p1;
    }
}

// ---------------------------------------------------------------------------
extern "C" void kernel_launch(void* const* d_in, const int* in_sizes, int n_in,
                              void* d_out, int out_size)
{
    const float* hs    = (const float*)d_in[0];
    const float* cos_t = (const float*)d_in[1];
    const float* sin_t = (const float*)d_in[2];
    const float* wqkv  = (const float*)d_in[3];
    const float* wo    = (const float*)d_in[4];
    float* out = (float*)d_out;

    __half *hs_f, *wq_h, *wo_h, *ctx, *qf, *kf, *vf;
    cudaGetSymbolAddress((void**)&hs_f, g_hs_f);
    cudaGetSymbolAddress((void**)&wq_h, g_wq_h);
    cudaGetSymbolAddress((void**)&wo_h, g_wo_h);
    cudaGetSymbolAddress((void**)&ctx,  g_ctx);
    cudaGetSymbolAddress((void**)&qf,   g_qf);
    cudaGetSymbolAddress((void**)&kf,   g_kf);
    cudaGetSymbolAddress((void**)&vf,   g_vf);

    // 0) converts (all plain fp16)
    conv_f16<<<MROWS * HIDDEN / 4 / 256, 256>>>(hs, hs_f, MROWS * HIDDEN / 4);
    conv_f16<<<QKV_O * HIDDEN / 4 / 256, 256>>>(wqkv, wq_h, QKV_O * HIDDEN / 4);
    conv_f16<<<HIDDEN * HIDDEN / 4 / 256, 256>>>(wo, wo_h, HIDDEN * HIDDEN / 4);

    const int gsm = NSTG * STGB;  // 80 KB
    cudaFuncSetAttribute(gemm_qkv_rope, cudaFuncAttributeMaxDynamicSharedMemorySize, gsm);
    cudaFuncSetAttribute(gemm_f16p4, cudaFuncAttributeMaxDynamicSharedMemorySize, gsm);

    // 1) QKV GEMM + fused RoPE + head-major fp16 layout
    gemm_qkv_rope<<<dim3(QKV_O / 128, MROWS / 128), 256, gsm>>>(
        hs_f, wq_h, cos_t, sin_t, qf, kf, vf);

    // 2) Flash attention (fp16 x1 HMMA, double-buffered K/V, big-first)
    flash_attn_f16<<<dim3(TT / 64, NH, BB), 128>>>(qf, kf, vf, ctx);

    // 3) out = ctx @ wo^T
    gemm_f16p4<<<dim3(HIDDEN / 128, MROWS / 128), 256, gsm>>>(
        ctx, wo_h, out, HIDDEN, HIDDEN);
}

// round 17
// speedup vs baseline: 1.0857x; 1.0621x over previous
#include <cuda_runtime.h>
#include <cuda_bf16.h>
#include <cuda_fp16.h>
#include <cstdint>
#include <math.h>

#define BB 2
#define TT 2048
#define HIDDEN 1024
#define NH 16
#define QKV_O 3072   // (16 + 2*16) * 64
#define MROWS (BB*TT) // 4096

// Scratch (allocation-free rule: __device__ globals)
__device__ __half g_hs_f[(size_t)MROWS * HIDDEN];
__device__ __half g_wq_h[(size_t)QKV_O * HIDDEN];
__device__ __half g_wo_h[(size_t)HIDDEN * HIDDEN];
__device__ __half g_ctx[(size_t)MROWS * HIDDEN];
// head-major fp16 attention operands: [b, h, t, d]
__device__ __half g_qf[(size_t)BB * NH * TT * 64];
__device__ __half g_kf[(size_t)BB * NH * TT * 64];
__device__ __half g_vf[(size_t)BB * NH * TT * 64];

// ===========================================================================
// Helpers
// ===========================================================================
__device__ __forceinline__ uint32_t smem_to_u32(const void* p) {
    uint32_t a;
    asm("{ .reg .u64 t; cvta.to.shared.u64 t, %1; cvt.u32.u64 %0, t; }" : "=r"(a) : "l"(p));
    return a;
}
__device__ __forceinline__ void ldsm4(unsigned* r, uint32_t addr) {
    asm volatile("ldmatrix.sync.aligned.m8n8.x4.shared.b16 {%0,%1,%2,%3}, [%4];"
                 : "=r"(r[0]), "=r"(r[1]), "=r"(r[2]), "=r"(r[3]) : "r"(addr));
}
__device__ __forceinline__ void ldsm4t(unsigned* r, uint32_t addr) {
    asm volatile("ldmatrix.sync.aligned.m8n8.x4.trans.shared.b16 {%0,%1,%2,%3}, [%4];"
                 : "=r"(r[0]), "=r"(r[1]), "=r"(r[2]), "=r"(r[3]) : "r"(addr));
}
__device__ __forceinline__ void mma_f16(float* c, const unsigned* a, unsigned b0, unsigned b1) {
    asm volatile("mma.sync.aligned.m16n8k16.row.col.f32.f16.f16.f32 "
                 "{%0,%1,%2,%3}, {%4,%5,%6,%7}, {%8,%9}, {%0,%1,%2,%3};"
                 : "+f"(c[0]), "+f"(c[1]), "+f"(c[2]), "+f"(c[3])
                 : "r"(a[0]), "r"(a[1]), "r"(a[2]), "r"(a[3]), "r"(b0), "r"(b1));
}
__device__ __forceinline__ unsigned pkH(float x, float y) {
    __half2 p(__float2half_rn(x), __float2half_rn(y));
    return *(unsigned*)&p;
}
#define CP_ASYNC16(dst, src) \
    asm volatile("cp.async.cg.shared.global [%0], [%1], 16;" :: "r"(dst), "l"(src))
#define CP_COMMIT() asm volatile("cp.async.commit_group;" ::: "memory")
#define CP_WAITG(n) asm volatile("cp.async.wait_group %0;" :: "n"(n) : "memory")

// ===========================================================================
// Converter (fp32 -> fp16)
// ===========================================================================
__global__ __launch_bounds__(256) void conv_f16(const float* __restrict__ x,
                                                __half* __restrict__ h, int n4)
{
    int i = blockIdx.x * blockDim.x + threadIdx.x;
    if (i >= n4) return;
    float4 v = ((const float4*)x)[i];
    __half2 p0 = __floats2half2_rn(v.x, v.y);
    __half2 p1 = __floats2half2_rn(v.z, v.w);
    uint2 o; o.x = *(uint32_t*)&p0; o.y = *(uint32_t*)&p1;
    ((uint2*)h)[i] = o;
}

// ===========================================================================
// QKV GEMM fused with RoPE + head-major fp16 output.
// Pair-synced 4-stage cp.async mainloop: 1 barrier per 2 chunks (64 MMAs/warp).
// Epilogue: fp32 tile staged in smem, RoPE on (d, d+32) pairs, half2 stores.
// ===========================================================================
#define SA 40
#define TSB (128 * SA * 2)        // one operand tile (10240 B)
#define STGB (2 * TSB)            // per-stage: A + B (20480 B)
#define NSTG 4                    // 80 KB total
#define CLD 132                   // fp32 staging stride

__global__ __launch_bounds__(256) void gemm_qkv_rope(const __half* __restrict__ A,
                                                     const __half* __restrict__ Bm,
                                                     const float* __restrict__ cos_t,
                                                     const float* __restrict__ sin_t,
                                                     __half* __restrict__ qf,
                                                     __half* __restrict__ kf,
                                                     __half* __restrict__ vf)
{
    extern __shared__ char dsm[];
    const uint32_t sbase = smem_to_u32(dsm);
    const int K = HIDDEN;

    const int tid  = threadIdx.x;
    const int wid  = tid >> 5;
    const int lane = tid & 31;
    const int warp_m = wid >> 2;
    const int warp_n = wid & 3;
    const int bm = blockIdx.y * 128;
    const int bn = blockIdx.x * 128;
    const int lj = lane & 7;
    const int li = lane >> 3;

    float c[4][4][4];
#pragma unroll
    for (int mt = 0; mt < 4; mt++)
#pragma unroll
        for (int nt = 0; nt < 4; nt++)
#pragma unroll
            for (int j = 0; j < 4; j++) c[mt][nt][j] = 0.f;

    const int a_row_base = warp_m * 64 + lj + ((li & 1) << 3);
    const int a_col_base = (li >> 1) << 3;
    const int b_row = warp_n * 32 + li * 8 + lj;

    // load two chunks (one pair), single commit
    auto load_pair = [&](int p) {
#pragma unroll
        for (int hc = 0; hc < 2; hc++) {
            const int ch = 2 * p + hc;
            const int stg = ch & 3;
#pragma unroll
            for (int i = 0; i < 4; i++) {
                const int tile = i >> 1;
                const int v = ((i & 1) << 8) + tid;
                const int r = v >> 2;
                const int c8 = (v & 3) << 3;
                const __half* sp = (tile == 0) ? A : Bm;
                const int grow = ((tile == 0) ? bm : bn) + r;
                uint32_t dst = sbase + stg * STGB + tile * TSB + (uint32_t)(r * SA + c8) * 2;
                CP_ASYNC16(dst, sp + (size_t)grow * K + ch * 32 + c8);
            }
        }
        CP_COMMIT();
    };

    const int npairs = (K >> 5) >> 1;   // 16
    load_pair(0);

    for (int p = 0; p < npairs; p++) {
        CP_WAITG(0);
        __syncthreads();
        if (p + 1 < npairs) load_pair(p + 1);   // overlaps full pair compute

#pragma unroll
        for (int hc = 0; hc < 2; hc++) {
            const uint32_t base = sbase + ((2 * p + hc) & 3) * STGB;
            const uint32_t oB = TSB;
#pragma unroll
            for (int ks = 0; ks < 2; ks++) {
                const int k0 = ks * 16;
                unsigned bh[2][4];
#pragma unroll
                for (int kh = 0; kh < 2; kh++) {
                    uint32_t ba = base + oB + (uint32_t)(b_row * SA + k0 + kh * 8) * 2;
                    ldsm4(bh[kh], ba);
                }
#pragma unroll
                for (int mt = 0; mt < 4; mt++) {
                    unsigned a[4];
                    uint32_t aa = base + (uint32_t)((a_row_base + mt * 16) * SA + k0 + a_col_base) * 2;
                    ldsm4(a, aa);
#pragma unroll
                    for (int nt = 0; nt < 4; nt++)
                        mma_f16(c[mt][nt], a, bh[0][nt], bh[1][nt]);
                }
            }
        }
    }

    // ---- epilogue: stage fp32 tile in smem ----
    __syncthreads();
    float* smc = (float*)dsm;              // 128 x CLD fp32 (67.6 KB <= 80 KB)
    const int q  = lane >> 2;
    const int t4 = lane & 3;
#pragma unroll
    for (int mt = 0; mt < 4; mt++) {
        int r0 = warp_m * 64 + mt * 16 + q;
#pragma unroll
        for (int nt = 0; nt < 4; nt++) {
            int col = warp_n * 32 + nt * 8 + 2 * t4;
            *(float2*)&smc[r0 * CLD + col] = make_float2(c[mt][nt][0], c[mt][nt][1]);
            *(float2*)&smc[(r0 + 8) * CLD + col] = make_float2(c[mt][nt][2], c[mt][nt][3]);
        }
    }
    __syncthreads();

    // ---- RoPE + head-major fp16 writes: 4096 (r, hh, d2)-units, half2 I/O ----
    const int ghead0 = bn >> 6;            // first head in this tile (2 heads)
#pragma unroll
    for (int i = 0; i < 16; i++) {
        int e = i * 256 + tid;             // 0..4095
        int r  = e >> 5;                   // 0..127
        int hh = (e >> 4) & 1;
        int d  = (e & 15) << 1;            // even d
        float2 x1 = *(float2*)&smc[r * CLD + hh * 64 + d];
        float2 x2 = *(float2*)&smc[r * CLD + hh * 64 + d + 32];
        int bt = bm + r;
        int t = bt & (TT - 1);
        int b = bt >> 11;
        int gh = ghead0 + hh;
        if (gh < 32) {                     // Q or K: RoPE
            float2 cc = *(const float2*)&cos_t[t * 64 + d];
            float2 ss = *(const float2*)&sin_t[t * 64 + d];
            float y1a = x1.x * cc.x - x2.x * ss.x;
            float y1b = x1.y * cc.y - x2.y * ss.y;
            float y2a = x2.x * cc.x + x1.x * ss.x;
            float y2b = x2.y * cc.y + x1.y * ss.y;
            if (gh < NH) {
                y1a *= 0.125f; y1b *= 0.125f; y2a *= 0.125f; y2b *= 0.125f;
                size_t dst = (((size_t)(b * NH + gh)) * TT + t) * 64 + d;
                __half2 h1(__float2half_rn(y1a), __float2half_rn(y1b));
                __half2 h2(__float2half_rn(y2a), __float2half_rn(y2b));
                *(__half2*)&qf[dst]      = h1;
                *(__half2*)&qf[dst + 32] = h2;
            } else {
                size_t dst = (((size_t)(b * NH + gh - NH)) * TT + t) * 64 + d;
                __half2 h1(__float2half_rn(y1a), __float2half_rn(y1b));
                __half2 h2(__float2half_rn(y2a), __float2half_rn(y2b));
                *(__half2*)&kf[dst]      = h1;
                *(__half2*)&kf[dst + 32] = h2;
            }
        } else {                           // V
            size_t dst = (((size_t)(b * NH + gh - 32)) * TT + t) * 64 + d;
            __half2 h1(__float2half_rn(x1.x), __float2half_rn(x1.y));
            __half2 h2(__float2half_rn(x2.x), __float2half_rn(x2.y));
            *(__half2*)&vf[dst]      = h1;
            *(__half2*)&vf[dst + 32] = h2;
        }
    }
}

// ===========================================================================
// fp16x1 HMMA GEMM (pair-synced 4-stage): C[.., ldc] = A[M,K]*B[N,K]^T
// Used for the O-projection.
// ===========================================================================
__global__ __launch_bounds__(256) void gemm_f16p4(const __half* __restrict__ A,
                                                  const __half* __restrict__ Bm,
                                                  float* __restrict__ C,
                                                  int ldc, int K)
{
    extern __shared__ char dsm[];
    const uint32_t sbase = smem_to_u32(dsm);

    const int tid  = threadIdx.x;
    const int wid  = tid >> 5;
    const int lane = tid & 31;
    const int warp_m = wid >> 2;
    const int warp_n = wid & 3;
    const int bm = blockIdx.y * 128;
    const int bn = blockIdx.x * 128;
    const int lj = lane & 7;
    const int li = lane >> 3;

    float c[4][4][4];
#pragma unroll
    for (int mt = 0; mt < 4; mt++)
#pragma unroll
        for (int nt = 0; nt < 4; nt++)
#pragma unroll
            for (int j = 0; j < 4; j++) c[mt][nt][j] = 0.f;

    const int a_row_base = warp_m * 64 + lj + ((li & 1) << 3);
    const int a_col_base = (li >> 1) << 3;
    const int b_row = warp_n * 32 + li * 8 + lj;

    auto load_pair = [&](int p) {
#pragma unroll
        for (int hc = 0; hc < 2; hc++) {
            const int ch = 2 * p + hc;
            const int stg = ch & 3;
#pragma unroll
            for (int i = 0; i < 4; i++) {
                const int tile = i >> 1;
                const int v = ((i & 1) << 8) + tid;
                const int r = v >> 2;
                const int c8 = (v & 3) << 3;
                const __half* sp = (tile == 0) ? A : Bm;
                const int grow = ((tile == 0) ? bm : bn) + r;
                uint32_t dst = sbase + stg * STGB + tile * TSB + (uint32_t)(r * SA + c8) * 2;
                CP_ASYNC16(dst, sp + (size_t)grow * K + ch * 32 + c8);
            }
        }
        CP_COMMIT();
    };

    const int npairs = (K >> 5) >> 1;
    load_pair(0);

    for (int p = 0; p < npairs; p++) {
        CP_WAITG(0);
        __syncthreads();
        if (p + 1 < npairs) load_pair(p + 1);

#pragma unroll
        for (int hc = 0; hc < 2; hc++) {
            const uint32_t base = sbase + ((2 * p + hc) & 3) * STGB;
            const uint32_t oB = TSB;
#pragma unroll
            for (int ks = 0; ks < 2; ks++) {
                const int k0 = ks * 16;
                unsigned bh[2][4];
#pragma unroll
                for (int kh = 0; kh < 2; kh++) {
                    uint32_t ba = base + oB + (uint32_t)(b_row * SA + k0 + kh * 8) * 2;
                    ldsm4(bh[kh], ba);
                }
#pragma unroll
                for (int mt = 0; mt < 4; mt++) {
                    unsigned a[4];
                    uint32_t aa = base + (uint32_t)((a_row_base + mt * 16) * SA + k0 + a_col_base) * 2;
                    ldsm4(a, aa);
#pragma unroll
                    for (int nt = 0; nt < 4; nt++)
                        mma_f16(c[mt][nt], a, bh[0][nt], bh[1][nt]);
                }
            }
        }
    }

    const int q  = lane >> 2;
    const int t4 = lane & 3;
#pragma unroll
    for (int mt = 0; mt < 4; mt++) {
        int row0 = bm + warp_m * 64 + mt * 16 + q;
#pragma unroll
        for (int nt = 0; nt < 4; nt++) {
            int col = bn + warp_n * 32 + nt * 8 + 2 * t4;
            *(float2*)&C[(size_t)row0 * ldc + col] =
                make_float2(c[mt][nt][0], c[mt][nt][1]);
            *(float2*)&C[(size_t)(row0 + 8) * ldc + col] =
                make_float2(c[mt][nt][2], c[mt][nt][3]);
        }
    }
}

// ===========================================================================
// fp16x1 HMMA flash attention (proven), double-buffered K/V, big-first.
// ===========================================================================
#define FSA 72
#define FT (64 * FSA)

__global__ __launch_bounds__(128) void flash_attn_f16(const __half* __restrict__ Qf,
                                                      const __half* __restrict__ Kf,
                                                      const __half* __restrict__ Vf,
                                                      __half* __restrict__ ctx)
{
    __shared__ __half sm_[5 * FT];
    const uint32_t sbase = smem_to_u32(sm_);

    const int qt = gridDim.x - 1 - blockIdx.x;   // big tiles first
    const int h  = blockIdx.y;
    const int b  = blockIdx.z;
    const int tid  = threadIdx.x;
    const int wid  = tid >> 5;
    const int lane = tid & 31;
    const int lj = lane & 7;
    const int li = lane >> 3;
    const int g  = lane >> 2;
    const int t4 = lane & 3;
    const int wrow = wid * 16;

    const size_t headbase = ((size_t)(b * NH + h)) * TT * 64;

    auto load_kv = [&](int kt, int buf) {
#pragma unroll
        for (int i = 0; i < 8; i++) {
            int v = i * 128 + tid;
            int tile = v >> 9;
            int r = (v >> 3) & 63;
            int c8 = (v & 7) << 3;
            const __half* sp = tile ? Vf : Kf;
            uint32_t dst = sbase + (uint32_t)(FT * 2) * (1 + 2 * buf + tile)
                         + (uint32_t)(r * FSA + c8) * 2;
            CP_ASYNC16(dst, sp + headbase + (size_t)(kt * 64 + r) * 64 + c8);
        }
        CP_COMMIT();
    };

#pragma unroll
    for (int i = 0; i < 4; i++) {
        int v = i * 128 + tid;
        int r = v >> 3;
        int c8 = (v & 7) << 3;
        uint32_t dst = sbase + (uint32_t)(r * FSA + c8) * 2;
        CP_ASYNC16(dst, Qf + headbase + (size_t)(qt * 64 + r) * 64 + c8);
    }
    load_kv(0, 0);

    float m0 = -1e30f, m1 = -1e30f, l0 = 0.f, l1 = 0.f;
    float o[8][4];
#pragma unroll
    for (int nt = 0; nt < 8; nt++)
#pragma unroll
        for (int j = 0; j < 4; j++) o[nt][j] = 0.f;

    const int a_row = wrow + lj + ((li & 1) << 3);
    const int a_col = (li >> 1) << 3;
    const int b_row = li * 8 + lj;
    const int v_row = lj + ((li & 1) << 3);
    const int v_col = (lane >> 4) << 3;

    for (int kt = 0; kt <= qt; kt++) {
        const int buf = kt & 1;
        const bool pf = (kt + 1 <= qt);
        if (pf) load_kv(kt + 1, buf ^ 1);
        if (pf) { CP_WAITG(1); } else { CP_WAITG(0); }
        __syncthreads();

        const uint32_t oK = (uint32_t)(FT * 2) * (1 + 2 * buf);
        const uint32_t oV = oK + (uint32_t)(FT * 2);

        float s[8][4];
#pragma unroll
        for (int nt = 0; nt < 8; nt++)
#pragma unroll
            for (int j = 0; j < 4; j++) s[nt][j] = 0.f;

#pragma unroll
        for (int ks = 0; ks < 4; ks++) {
            const int k0 = ks * 16;
            unsigned a[4];
            uint32_t aa = sbase + (uint32_t)(a_row * FSA + k0 + a_col) * 2;
            ldsm4(a, aa);
#pragma unroll
            for (int nh = 0; nh < 2; nh++) {
                unsigned kfr[2][4];
#pragma unroll
                for (int kh = 0; kh < 2; kh++) {
                    uint32_t ba = sbase + oK + (uint32_t)((b_row + nh * 32) * FSA + k0 + kh * 8) * 2;
                    ldsm4(kfr[kh], ba);
                }
#pragma unroll
                for (int nt = 0; nt < 4; nt++)
                    mma_f16(s[nh * 4 + nt], a, kfr[0][nt], kfr[1][nt]);
            }
        }

        if (kt == qt) {
            int r0 = wrow + g, r1 = r0 + 8;
#pragma unroll
            for (int nt = 0; nt < 8; nt++) {
                int c0 = nt * 8 + 2 * t4, c1 = c0 + 1;
                if (c0 > r0) s[nt][0] = -1e30f;
                if (c1 > r0) s[nt][1] = -1e30f;
                if (c0 > r1) s[nt][2] = -1e30f;
                if (c1 > r1) s[nt][3] = -1e30f;
            }
        }

        float mx0 = -1e30f, mx1 = -1e30f;
#pragma unroll
        for (int nt = 0; nt < 8; nt++) {
            mx0 = fmaxf(mx0, fmaxf(s[nt][0], s[nt][1]));
            mx1 = fmaxf(mx1, fmaxf(s[nt][2], s[nt][3]));
        }
        mx0 = fmaxf(mx0, __shfl_xor_sync(0xffffffffu, mx0, 1));
        mx0 = fmaxf(mx0, __shfl_xor_sync(0xffffffffu, mx0, 2));
        mx1 = fmaxf(mx1, __shfl_xor_sync(0xffffffffu, mx1, 1));
        mx1 = fmaxf(mx1, __shfl_xor_sync(0xffffffffu, mx1, 2));

        float mn0 = fmaxf(m0, mx0), mn1 = fmaxf(m1, mx1);
        float alpha0 = __expf(m0 - mn0), alpha1 = __expf(m1 - mn1);
        m0 = mn0; m1 = mn1;

        float sum0 = 0.f, sum1 = 0.f;
#pragma unroll
        for (int nt = 0; nt < 8; nt++) {
            s[nt][0] = __expf(s[nt][0] - mn0);
            s[nt][1] = __expf(s[nt][1] - mn0);
            s[nt][2] = __expf(s[nt][2] - mn1);
            s[nt][3] = __expf(s[nt][3] - mn1);
            sum0 += s[nt][0] + s[nt][1];
            sum1 += s[nt][2] + s[nt][3];
        }
        sum0 += __shfl_xor_sync(0xffffffffu, sum0, 1);
        sum0 += __shfl_xor_sync(0xffffffffu, sum0, 2);
        sum1 += __shfl_xor_sync(0xffffffffu, sum1, 1);
        sum1 += __shfl_xor_sync(0xffffffffu, sum1, 2);
        l0 = l0 * alpha0 + sum0;
        l1 = l1 * alpha1 + sum1;

#pragma unroll
        for (int nt = 0; nt < 8; nt++) {
            o[nt][0] *= alpha0; o[nt][1] *= alpha0;
            o[nt][2] *= alpha1; o[nt][3] *= alpha1;
        }

#pragma unroll
        for (int ks = 0; ks < 4; ks++) {
            const int k0 = ks * 16;
            unsigned a[4];
            {
                float* p0 = s[2 * ks];
                float* p1 = s[2 * ks + 1];
                a[0] = pkH(p0[0], p0[1]);
                a[1] = pkH(p0[2], p0[3]);
                a[2] = pkH(p1[0], p1[1]);
                a[3] = pkH(p1[2], p1[3]);
            }
#pragma unroll
            for (int nh = 0; nh < 4; nh++) {
                uint32_t va = sbase + oV + (uint32_t)((k0 + v_row) * FSA + nh * 16 + v_col) * 2;
                unsigned vfr[4];
                ldsm4t(vfr, va);
                mma_f16(o[nh * 2],     a, vfr[0], vfr[1]);
                mma_f16(o[nh * 2 + 1], a, vfr[2], vfr[3]);
            }
        }
        __syncthreads();
    }

    float inv0 = 1.f / l0, inv1 = 1.f / l1;
    int row0 = qt * 64 + wrow + g;
    size_t base0 = ((size_t)(b * TT + row0)) * HIDDEN + h * 64;
    size_t base1 = base0 + 8 * HIDDEN;
#pragma unroll
    for (int nt = 0; nt < 8; nt++) {
        int c = nt * 8 + 2 * t4;
        __half2 p0 = __floats2half2_rn(o[nt][0] * inv0, o[nt][1] * inv0);
        __half2 p1 = __floats2half2_rn(o[nt][2] * inv1, o[nt][3] * inv1);
        *(unsigned*)&ctx[base0 + c] = *(unsigned*)&p0;
        *(unsigned*)&ctx[base1 + c] = *(unsigned*)&p1;
    }
}

// ---------------------------------------------------------------------------
extern "C" void kernel_launch(void* const* d_in, const int* in_sizes, int n_in,
                              void* d_out, int out_size)
{
    const float* hs    = (const float*)d_in[0];
    const float* cos_t = (const float*)d_in[1];
    const float* sin_t = (const float*)d_in[2];
    const float* wqkv  = (const float*)d_in[3];
    const float* wo    = (const float*)d_in[4];
    float* out = (float*)d_out;

    __half *hs_f, *wq_h, *wo_h, *ctx, *qf, *kf, *vf;
    cudaGetSymbolAddress((void**)&hs_f, g_hs_f);
    cudaGetSymbolAddress((void**)&wq_h, g_wq_h);
    cudaGetSymbolAddress((void**)&wo_h, g_wo_h);
    cudaGetSymbolAddress((void**)&ctx,  g_ctx);
    cudaGetSymbolAddress((void**)&qf,   g_qf);
    cudaGetSymbolAddress((void**)&kf,   g_kf);
    cudaGetSymbolAddress((void**)&vf,   g_vf);

    // 0) converts (all plain fp16)
    conv_f16<<<MROWS * HIDDEN / 4 / 256, 256>>>(hs, hs_f, MROWS * HIDDEN / 4);
    conv_f16<<<QKV_O * HIDDEN / 4 / 256, 256>>>(wqkv, wq_h, QKV_O * HIDDEN / 4);
    conv_f16<<<HIDDEN * HIDDEN / 4 / 256, 256>>>(wo, wo_h, HIDDEN * HIDDEN / 4);

    const int gsm = NSTG * STGB;  // 80 KB
    cudaFuncSetAttribute(gemm_qkv_rope, cudaFuncAttributeMaxDynamicSharedMemorySize, gsm);
    cudaFuncSetAttribute(gemm_f16p4, cudaFuncAttributeMaxDynamicSharedMemorySize, gsm);

    // 1) QKV GEMM + fused RoPE + head-major fp16 layout
    gemm_qkv_rope<<<dim3(QKV_O / 128, MROWS / 128), 256, gsm>>>(
        hs_f, wq_h, cos_t, sin_t, qf, kf, vf);

    // 2) Flash attention (fp16 x1 HMMA, double-buffered K/V, big-first)
    flash_attn_f16<<<dim3(TT / 64, NH, BB), 128>>>(qf, kf, vf, ctx);

    // 3) out = ctx @ wo^T
    gemm_f16p4<<<dim3(HIDDEN / 128, MROWS / 128), 256, gsm>>>(
        ctx, wo_h, out, HIDDEN, HIDDEN);
}